// round 14
// baseline (speedup 1.0000x reference)
#include <cuda_runtime.h>

// Problem constants: B=8192, T=64, D=512
#define BB 8192
#define TT 64
#define DD 512

__device__ __forceinline__ float warp_reduce_sum(float v) {
    #pragma unroll
    for (int off = 16; off > 0; off >>= 1)
        v += __shfl_xor_sync(0xFFFFFFFFu, v, off);
    return v;
}

// streaming (evict-first) loads/stores for single-use data
__device__ __forceinline__ float4 ldcs4(const float4* p) { return __ldcs(p); }
__device__ __forceinline__ float2 ldcs2(const float2* p) { return __ldcs(p); }

__global__ __launch_bounds__(256)
void sdpa_decode_kernel(const float* __restrict__ q,
                        const float* __restrict__ k,
                        const float* __restrict__ v,
                        const int*   __restrict__ pad_mask,
                        float* __restrict__ out,       // [B, D]
                        float* __restrict__ attn_out)  // [B, T]
{
    const int b    = blockIdx.x;
    const int tid  = threadIdx.x;
    const int warp = tid >> 5;
    const int lane = tid & 31;

    const float INV_TEMP  = 0.04419417382415922f;   // 1/sqrt(512)
    const float MASK_FILL = -1000.0f;

    __shared__ float4 qs[DD / 4];     // q row: 128 float4
    __shared__ float  s_logit[TT];
    __shared__ int    s_mask[TT];
    __shared__ float  s_p[TT];        // compacted probabilities
    __shared__ int    s_t[TT];        // compacted t indices
    __shared__ int    s_n;

    // ---- load q[b] and pad_mask[b] into shared (both single-use: streaming) ----
    const float4* q4 = reinterpret_cast<const float4*>(q + (size_t)b * DD);
    if (tid < DD / 4) qs[tid] = __ldcs(q4 + tid);
    if (tid < TT)     s_mask[tid] = __ldcs(pad_mask + (size_t)b * TT + tid);
    __syncthreads();

    // ---- QK^T: warp w owns rows {w, w+8, w+16, ..}; process in PAIRS for MLP ----
    const float4* kbase = reinterpret_cast<const float4*>(k + (size_t)b * TT * DD);
    #pragma unroll
    for (int ti = 0; ti < 4; ti++) {
        const int ta = warp + ti * 16;          // first row of pair
        const int tb = ta + 8;                  // second row of pair
        const int ma = s_mask[ta];
        const int mb = s_mask[tb];
        if (!ma && !mb) {
            // both active: 8 independent LDG.128 before the reduces
            const float4* ka = kbase + (size_t)ta * (DD / 4);
            const float4* kb = kbase + (size_t)tb * (DD / 4);
            float pa = 0.0f, pb = 0.0f;
            #pragma unroll
            for (int j = 0; j < 4; j++) {
                const int idx = lane + j * 32;
                float4 av = ldcs4(ka + idx);
                float4 bv = ldcs4(kb + idx);
                float4 qv = qs[idx];
                pa += av.x * qv.x + av.y * qv.y + av.z * qv.z + av.w * qv.w;
                pb += bv.x * qv.x + bv.y * qv.y + bv.z * qv.z + bv.w * qv.w;
            }
            pa = warp_reduce_sum(pa);
            pb = warp_reduce_sum(pb);
            if (lane == 0) { s_logit[ta] = pa; s_logit[tb] = pb; }
        } else if (!ma || !mb) {
            // exactly one active
            const int t = ma ? tb : ta;
            const float4* kr = kbase + (size_t)t * (DD / 4);
            float p = 0.0f;
            #pragma unroll
            for (int j = 0; j < 4; j++) {
                const int idx = lane + j * 32;
                float4 kv = ldcs4(kr + idx);
                float4 qv = qs[idx];
                p += kv.x * qv.x + kv.y * qv.y + kv.z * qv.z + kv.w * qv.w;
            }
            p = warp_reduce_sum(p);
            if (lane == 0) s_logit[t] = p;
        }
    }
    __syncthreads();

    // ---- masked softmax (warp 0, 2 values/lane) + ballot compaction ----
    if (warp == 0) {
        float v0 = s_mask[lane]      ? MASK_FILL : s_logit[lane]      * INV_TEMP;
        float v1 = s_mask[lane + 32] ? MASK_FILL : s_logit[lane + 32] * INV_TEMP;

        float m = fmaxf(v0, v1);
        #pragma unroll
        for (int off = 16; off > 0; off >>= 1)
            m = fmaxf(m, __shfl_xor_sync(0xFFFFFFFFu, m, off));

        float e0 = __expf(v0 - m);   // underflows to exact 0 for masked (matches ref)
        float e1 = __expf(v1 - m);
        float ssum = warp_reduce_sum(e0 + e1);
        float inv = 1.0f / ssum;
        float p0 = e0 * inv;
        float p1 = e1 * inv;

        // streaming stores: attention output is write-once
        __stcs(attn_out + (size_t)b * TT + lane,      p0);
        __stcs(attn_out + (size_t)b * TT + lane + 32, p1);

        // compact nonzero-probability rows (handles all-masked edge case too)
        bool a0 = (p0 != 0.0f);
        bool a1 = (p1 != 0.0f);
        unsigned b0 = __ballot_sync(0xFFFFFFFFu, a0);
        unsigned b1 = __ballot_sync(0xFFFFFFFFu, a1);
        int n0 = __popc(b0);
        unsigned lt = (1u << lane) - 1u;
        if (a0) { int pos = __popc(b0 & lt);       s_t[pos] = lane;      s_p[pos] = p0; }
        if (a1) { int pos = n0 + __popc(b1 & lt);  s_t[pos] = lane + 32; s_p[pos] = p1; }
        if (lane == 0) s_n = n0 + __popc(b1);
    }
    __syncthreads();

    // ---- P·V over ACTIVE rows; 256 threads x float2, unroll x8, int offsets ----
    const float2* vbase = reinterpret_cast<const float2*>(v + (size_t)b * TT * DD);
    const int d2 = tid;                 // float2 index 0..255
    const int n  = s_n;
    float2 acc = make_float2(0.0f, 0.0f);

    int i = 0;
    for (; i + 8 <= n; i += 8) {
        float p0 = s_p[i],   p1 = s_p[i+1], p2 = s_p[i+2], p3 = s_p[i+3];
        float p4 = s_p[i+4], p5 = s_p[i+5], p6 = s_p[i+6], p7 = s_p[i+7];
        int o0 = s_t[i]   * (DD / 2) + d2;
        int o1 = s_t[i+1] * (DD / 2) + d2;
        int o2 = s_t[i+2] * (DD / 2) + d2;
        int o3 = s_t[i+3] * (DD / 2) + d2;
        int o4 = s_t[i+4] * (DD / 2) + d2;
        int o5 = s_t[i+5] * (DD / 2) + d2;
        int o6 = s_t[i+6] * (DD / 2) + d2;
        int o7 = s_t[i+7] * (DD / 2) + d2;
        float2 v0 = ldcs2(vbase + o0), v1 = ldcs2(vbase + o1);
        float2 v2 = ldcs2(vbase + o2), v3 = ldcs2(vbase + o3);
        float2 v4 = ldcs2(vbase + o4), v5 = ldcs2(vbase + o5);
        float2 v6 = ldcs2(vbase + o6), v7 = ldcs2(vbase + o7);
        acc.x += p0 * v0.x; acc.y += p0 * v0.y;
        acc.x += p1 * v1.x; acc.y += p1 * v1.y;
        acc.x += p2 * v2.x; acc.y += p2 * v2.y;
        acc.x += p3 * v3.x; acc.y += p3 * v3.y;
        acc.x += p4 * v4.x; acc.y += p4 * v4.y;
        acc.x += p5 * v5.x; acc.y += p5 * v5.y;
        acc.x += p6 * v6.x; acc.y += p6 * v6.y;
        acc.x += p7 * v7.x; acc.y += p7 * v7.y;
    }
    for (; i + 4 <= n; i += 4) {
        float pa = s_p[i],   pb = s_p[i+1], pc = s_p[i+2], pd = s_p[i+3];
        int oa = s_t[i]   * (DD / 2) + d2;
        int ob = s_t[i+1] * (DD / 2) + d2;
        int oc = s_t[i+2] * (DD / 2) + d2;
        int od = s_t[i+3] * (DD / 2) + d2;
        float2 va = ldcs2(vbase + oa), vb = ldcs2(vbase + ob);
        float2 vc = ldcs2(vbase + oc), vd = ldcs2(vbase + od);
        acc.x += pa * va.x; acc.y += pa * va.y;
        acc.x += pb * vb.x; acc.y += pb * vb.y;
        acc.x += pc * vc.x; acc.y += pc * vc.y;
        acc.x += pd * vd.x; acc.y += pd * vd.y;
    }
    for (; i < n; i++) {
        float  p  = s_p[i];
        float2 vv = ldcs2(vbase + s_t[i] * (DD / 2) + d2);
        acc.x += p * vv.x; acc.y += p * vv.y;
    }
    // streaming store: output row is write-once
    __stcs(reinterpret_cast<float2*>(out + (size_t)b * DD) + d2, acc);
}

extern "C" void kernel_launch(void* const* d_in, const int* in_sizes, int n_in,
                              void* d_out, int out_size) {
    const float* q        = (const float*)d_in[0];   // [B, D]
    const float* k        = (const float*)d_in[1];   // [B, T, D]
    const float* v        = (const float*)d_in[2];   // [B, T, D]
    const int*   pad_mask = (const int*)  d_in[3];   // [B, T]

    float* out      = (float*)d_out;                   // [B,1,D]
    float* attn_out = (float*)d_out + (size_t)BB * DD; // [B,1,T]

    sdpa_decode_kernel<<<BB, 256>>>(q, k, v, pad_mask, out, attn_out);
}

// round 15
// speedup vs baseline: 1.0586x; 1.0586x over previous
#include <cuda_runtime.h>

// Problem constants: B=8192, T=64, D=512
#define BB 8192
#define TT 64
#define DD 512

__device__ __forceinline__ float warp_reduce_sum(float v) {
    #pragma unroll
    for (int off = 16; off > 0; off >>= 1)
        v += __shfl_xor_sync(0xFFFFFFFFu, v, off);
    return v;
}

// streaming (evict-first) float4 / float2 loads for single-use K/V data
__device__ __forceinline__ float4 ldcs4(const float4* p) { return __ldcs(p); }
__device__ __forceinline__ float2 ldcs2(const float2* p) { return __ldcs(p); }

__global__ __launch_bounds__(256)
void sdpa_decode_kernel(const float* __restrict__ q,
                        const float* __restrict__ k,
                        const float* __restrict__ v,
                        const int*   __restrict__ pad_mask,
                        float* __restrict__ out,       // [B, D]
                        float* __restrict__ attn_out)  // [B, T]
{
    const int b    = blockIdx.x;
    const int tid  = threadIdx.x;
    const int warp = tid >> 5;
    const int lane = tid & 31;

    const float INV_TEMP  = 0.04419417382415922f;   // 1/sqrt(512)
    const float MASK_FILL = -1000.0f;

    __shared__ float4 qs[DD / 4];     // q row: 128 float4
    __shared__ float  s_logit[TT];
    __shared__ int    s_mask[TT];
    __shared__ float  s_p[TT];        // compacted probabilities
    __shared__ int    s_t[TT];        // compacted t indices
    __shared__ int    s_n;

    // ---- load q[b] and pad_mask[b] into shared (default caching: reused) ----
    const float4* q4 = reinterpret_cast<const float4*>(q + (size_t)b * DD);
    if (tid < DD / 4) qs[tid] = q4[tid];
    if (tid < TT)     s_mask[tid] = pad_mask[(size_t)b * TT + tid];
    __syncthreads();

    // ---- QK^T: warp w owns rows {w, w+8, w+16, ..}; process in PAIRS for MLP ----
    const float4* kbase = reinterpret_cast<const float4*>(k + (size_t)b * TT * DD);
    #pragma unroll
    for (int ti = 0; ti < 4; ti++) {
        const int ta = warp + ti * 16;          // first row of pair
        const int tb = ta + 8;                  // second row of pair
        const int ma = s_mask[ta];
        const int mb = s_mask[tb];
        if (!ma && !mb) {
            // both active: 8 independent LDG.128 before the reduces
            const float4* ka = kbase + (size_t)ta * (DD / 4);
            const float4* kb = kbase + (size_t)tb * (DD / 4);
            float pa = 0.0f, pb = 0.0f;
            #pragma unroll
            for (int j = 0; j < 4; j++) {
                const int idx = lane + j * 32;
                float4 av = ldcs4(ka + idx);
                float4 bv = ldcs4(kb + idx);
                float4 qv = qs[idx];
                pa += av.x * qv.x + av.y * qv.y + av.z * qv.z + av.w * qv.w;
                pb += bv.x * qv.x + bv.y * qv.y + bv.z * qv.z + bv.w * qv.w;
            }
            pa = warp_reduce_sum(pa);
            pb = warp_reduce_sum(pb);
            if (lane == 0) { s_logit[ta] = pa; s_logit[tb] = pb; }
        } else if (!ma || !mb) {
            // exactly one active
            const int t = ma ? tb : ta;
            const float4* kr = kbase + (size_t)t * (DD / 4);
            float p = 0.0f;
            #pragma unroll
            for (int j = 0; j < 4; j++) {
                const int idx = lane + j * 32;
                float4 kv = ldcs4(kr + idx);
                float4 qv = qs[idx];
                p += kv.x * qv.x + kv.y * qv.y + kv.z * qv.z + kv.w * qv.w;
            }
            p = warp_reduce_sum(p);
            if (lane == 0) s_logit[t] = p;
        }
    }
    __syncthreads();

    // ---- masked softmax (warp 0, 2 values/lane) + ballot compaction ----
    if (warp == 0) {
        float v0 = s_mask[lane]      ? MASK_FILL : s_logit[lane]      * INV_TEMP;
        float v1 = s_mask[lane + 32] ? MASK_FILL : s_logit[lane + 32] * INV_TEMP;

        float m = fmaxf(v0, v1);
        #pragma unroll
        for (int off = 16; off > 0; off >>= 1)
            m = fmaxf(m, __shfl_xor_sync(0xFFFFFFFFu, m, off));

        float e0 = __expf(v0 - m);   // underflows to exact 0 for masked (matches ref)
        float e1 = __expf(v1 - m);
        float ssum = warp_reduce_sum(e0 + e1);
        float inv = 1.0f / ssum;
        float p0 = e0 * inv;
        float p1 = e1 * inv;

        attn_out[(size_t)b * TT + lane]      = p0;
        attn_out[(size_t)b * TT + lane + 32] = p1;

        // compact nonzero-probability rows (handles all-masked edge case too)
        bool a0 = (p0 != 0.0f);
        bool a1 = (p1 != 0.0f);
        unsigned b0 = __ballot_sync(0xFFFFFFFFu, a0);
        unsigned b1 = __ballot_sync(0xFFFFFFFFu, a1);
        int n0 = __popc(b0);
        unsigned lt = (1u << lane) - 1u;
        if (a0) { int pos = __popc(b0 & lt);       s_t[pos] = lane;      s_p[pos] = p0; }
        if (a1) { int pos = n0 + __popc(b1 & lt);  s_t[pos] = lane + 32; s_p[pos] = p1; }
        if (lane == 0) s_n = n0 + __popc(b1);
    }
    __syncthreads();

    // ---- P·V over ACTIVE rows; 256 threads x float2, unroll x8, int offsets ----
    const float2* vbase = reinterpret_cast<const float2*>(v + (size_t)b * TT * DD);
    const int d2 = tid;                 // float2 index 0..255
    const int n  = s_n;
    float2 acc = make_float2(0.0f, 0.0f);

    int i = 0;
    for (; i + 8 <= n; i += 8) {
        float p0 = s_p[i],   p1 = s_p[i+1], p2 = s_p[i+2], p3 = s_p[i+3];
        float p4 = s_p[i+4], p5 = s_p[i+5], p6 = s_p[i+6], p7 = s_p[i+7];
        int o0 = s_t[i]   * (DD / 2) + d2;
        int o1 = s_t[i+1] * (DD / 2) + d2;
        int o2 = s_t[i+2] * (DD / 2) + d2;
        int o3 = s_t[i+3] * (DD / 2) + d2;
        int o4 = s_t[i+4] * (DD / 2) + d2;
        int o5 = s_t[i+5] * (DD / 2) + d2;
        int o6 = s_t[i+6] * (DD / 2) + d2;
        int o7 = s_t[i+7] * (DD / 2) + d2;
        float2 v0 = ldcs2(vbase + o0), v1 = ldcs2(vbase + o1);
        float2 v2 = ldcs2(vbase + o2), v3 = ldcs2(vbase + o3);
        float2 v4 = ldcs2(vbase + o4), v5 = ldcs2(vbase + o5);
        float2 v6 = ldcs2(vbase + o6), v7 = ldcs2(vbase + o7);
        acc.x += p0 * v0.x; acc.y += p0 * v0.y;
        acc.x += p1 * v1.x; acc.y += p1 * v1.y;
        acc.x += p2 * v2.x; acc.y += p2 * v2.y;
        acc.x += p3 * v3.x; acc.y += p3 * v3.y;
        acc.x += p4 * v4.x; acc.y += p4 * v4.y;
        acc.x += p5 * v5.x; acc.y += p5 * v5.y;
        acc.x += p6 * v6.x; acc.y += p6 * v6.y;
        acc.x += p7 * v7.x; acc.y += p7 * v7.y;
    }
    for (; i + 4 <= n; i += 4) {
        float pa = s_p[i],   pb = s_p[i+1], pc = s_p[i+2], pd = s_p[i+3];
        int oa = s_t[i]   * (DD / 2) + d2;
        int ob = s_t[i+1] * (DD / 2) + d2;
        int oc = s_t[i+2] * (DD / 2) + d2;
        int od = s_t[i+3] * (DD / 2) + d2;
        float2 va = ldcs2(vbase + oa), vb = ldcs2(vbase + ob);
        float2 vc = ldcs2(vbase + oc), vd = ldcs2(vbase + od);
        acc.x += pa * va.x; acc.y += pa * va.y;
        acc.x += pb * vb.x; acc.y += pb * vb.y;
        acc.x += pc * vc.x; acc.y += pc * vc.y;
        acc.x += pd * vd.x; acc.y += pd * vd.y;
    }
    for (; i < n; i++) {
        float  p  = s_p[i];
        float2 vv = ldcs2(vbase + s_t[i] * (DD / 2) + d2);
        acc.x += p * vv.x; acc.y += p * vv.y;
    }
    reinterpret_cast<float2*>(out + (size_t)b * DD)[d2] = acc;
}

extern "C" void kernel_launch(void* const* d_in, const int* in_sizes, int n_in,
                              void* d_out, int out_size) {
    const float* q        = (const float*)d_in[0];   // [B, D]
    const float* k        = (const float*)d_in[1];   // [B, T, D]
    const float* v        = (const float*)d_in[2];   // [B, T, D]
    const int*   pad_mask = (const int*)  d_in[3];   // [B, T]

    float* out      = (float*)d_out;                   // [B,1,D]
    float* attn_out = (float*)d_out + (size_t)BB * DD; // [B,1,T]

    sdpa_decode_kernel<<<BB, 256>>>(q, k, v, pad_mask, out, attn_out);
}